// round 2
// baseline (speedup 1.0000x reference)
#include <cuda_runtime.h>
#include <math.h>

#define Bdim 8
#define Sdim 4096
#define Ddim 512
#define Mrows (Bdim * Sdim)   /* 32768 */
#define NC 32
#define CL (Sdim / NC)        /* 128 */

// ---------------------------------------------------------------------------
// Scratch (device globals — no allocation allowed)
// ---------------------------------------------------------------------------
__device__ float g_omega[(size_t)Mrows * Ddim];
__device__ float g_mag  [(size_t)Mrows * Ddim];
__device__ float g_gate [(size_t)Mrows * Ddim];
__device__ float g_qoff [(size_t)Mrows * Ddim];
__device__ float g_p1h  [(size_t)Mrows * Ddim];
__device__ float g_phii [(size_t)Mrows * Ddim];
__device__ float g_ctx  [(size_t)Mrows * 4 * Ddim];
__device__ float g_h    [(size_t)Mrows * 2 * Ddim];
__device__ float4 g_csum[Bdim * NC * Ddim];
__device__ float4 g_coff[Bdim * NC * Ddim];

// ---------------------------------------------------------------------------
// Packed f32x2 helpers (sm_103a: scalar FFMA is half-rate; f32x2 is full-rate)
// ---------------------------------------------------------------------------
__device__ __forceinline__ unsigned long long bcast2(float v) {
    unsigned long long r;
    unsigned u = __float_as_uint(v);
    asm("mov.b64 %0, {%1, %1};" : "=l"(r) : "r"(u));
    return r;
}
__device__ __forceinline__ void fma2(unsigned long long& d,
                                     unsigned long long a,
                                     unsigned long long b) {
    asm("fma.rn.f32x2 %0, %1, %2, %0;" : "+l"(d) : "l"(a), "l"(b));
}
__device__ __forceinline__ void unpack2(unsigned long long v, float& lo, float& hi) {
    unsigned a, b;
    asm("mov.b64 {%0, %1}, %2;" : "=r"(a), "=r"(b) : "l"(v));
    lo = __uint_as_float(a);
    hi = __uint_as_float(b);
}

// ---------------------------------------------------------------------------
// SGEMM: C[M,N] = act(A[M,K] @ W[K,N] + bias[N]) (+ resid for ACT==4)
// BM=BN=128, BK=8, 256 threads, 8x8 per thread, double-buffered smem,
// f32x2 packed inner product.
// ACT: 0=none 1=sigmoid 2=5*sigmoid 3=gelu(exact) 4=residual add
// Requires: M%128==0, N%128==0, K%8==0 (true for all launches here).
// ---------------------------------------------------------------------------
template <int ACT>
__global__ void __launch_bounds__(256, 2)
sgemm_kernel(const float* __restrict__ A,
             const float* __restrict__ W,
             const float* __restrict__ bias,
             const float* __restrict__ resid,
             float* __restrict__ C,
             int M, int N, int K)
{
    __shared__ float As[2][8][128];
    __shared__ float Bs[2][8][128];

    const int tid = threadIdx.x;
    const int tx = tid & 15;
    const int ty = tid >> 4;
    const int bn = blockIdx.x * 128;
    const int bm = blockIdx.y * 128;

    const int arow = tid >> 1;
    const int acol = (tid & 1) << 2;
    const int brow = tid >> 5;
    const int bcol = (tid & 31) << 2;

    const float* Aptr = A + (size_t)(bm + arow) * K + acol;
    const float* Wptr = W + (size_t)brow * N + bn + bcol;

    float4 av = *(const float4*)Aptr;
    float4 bv = *(const float4*)Wptr;
    As[0][acol + 0][arow] = av.x;
    As[0][acol + 1][arow] = av.y;
    As[0][acol + 2][arow] = av.z;
    As[0][acol + 3][arow] = av.w;
    *(float4*)&Bs[0][brow][bcol] = bv;
    __syncthreads();

    unsigned long long acc2[8][4];
    #pragma unroll
    for (int i = 0; i < 8; i++)
        #pragma unroll
        for (int p = 0; p < 4; p++) acc2[i][p] = 0ull;

    const int nk = K >> 3;
    for (int kt = 0; kt < nk; kt++) {
        const int cur = kt & 1;
        if (kt + 1 < nk) {
            av = *(const float4*)(Aptr + (kt + 1) * 8);
            bv = *(const float4*)(Wptr + (size_t)(kt + 1) * 8 * N);
        }
        #pragma unroll
        for (int k = 0; k < 8; k++) {
            float4 a0 = *(const float4*)&As[cur][k][ty * 8];
            float4 a1 = *(const float4*)&As[cur][k][ty * 8 + 4];
            ulonglong2 bq0 = *(const ulonglong2*)&Bs[cur][k][tx * 8];
            ulonglong2 bq1 = *(const ulonglong2*)&Bs[cur][k][tx * 8 + 4];
            unsigned long long aa[8];
            aa[0] = bcast2(a0.x); aa[1] = bcast2(a0.y);
            aa[2] = bcast2(a0.z); aa[3] = bcast2(a0.w);
            aa[4] = bcast2(a1.x); aa[5] = bcast2(a1.y);
            aa[6] = bcast2(a1.z); aa[7] = bcast2(a1.w);
            #pragma unroll
            for (int i = 0; i < 8; i++) {
                fma2(acc2[i][0], aa[i], bq0.x);
                fma2(acc2[i][1], aa[i], bq0.y);
                fma2(acc2[i][2], aa[i], bq1.x);
                fma2(acc2[i][3], aa[i], bq1.y);
            }
        }
        if (kt + 1 < nk) {
            const int nxt = cur ^ 1;
            As[nxt][acol + 0][arow] = av.x;
            As[nxt][acol + 1][arow] = av.y;
            As[nxt][acol + 2][arow] = av.z;
            As[nxt][acol + 3][arow] = av.w;
            *(float4*)&Bs[nxt][brow][bcol] = bv;
        }
        __syncthreads();
    }

    // Epilogue
    const float4 bias0 = *(const float4*)(bias + bn + tx * 8);
    const float4 bias1 = *(const float4*)(bias + bn + tx * 8 + 4);
    const float bb[8] = {bias0.x, bias0.y, bias0.z, bias0.w,
                         bias1.x, bias1.y, bias1.z, bias1.w};
    #pragma unroll
    for (int i = 0; i < 8; i++) {
        const int m = bm + ty * 8 + i;
        const size_t rowoff = (size_t)m * N + bn + tx * 8;
        float vals[8];
        #pragma unroll
        for (int p = 0; p < 4; p++)
            unpack2(acc2[i][p], vals[2 * p], vals[2 * p + 1]);
        #pragma unroll
        for (int j = 0; j < 8; j++) {
            float v = vals[j] + bb[j];
            if (ACT == 1) v = 1.0f / (1.0f + expf(-v));
            else if (ACT == 2) v = 5.0f / (1.0f + expf(-v));
            else if (ACT == 3) v = 0.5f * v * (1.0f + erff(v * 0.70710678118654752f));
            vals[j] = v;
        }
        if (ACT == 4) {
            float4 r0 = *(const float4*)(resid + rowoff);
            float4 r1 = *(const float4*)(resid + rowoff + 4);
            vals[0] += r0.x; vals[1] += r0.y; vals[2] += r0.z; vals[3] += r0.w;
            vals[4] += r1.x; vals[5] += r1.y; vals[6] += r1.z; vals[7] += r1.w;
        }
        float4 o0 = make_float4(vals[0], vals[1], vals[2], vals[3]);
        float4 o1 = make_float4(vals[4], vals[5], vals[6], vals[7]);
        *(float4*)&C[rowoff] = o0;
        *(float4*)&C[rowoff + 4] = o1;
    }
}

// ---------------------------------------------------------------------------
// Pass A: per-(b, chunk, d) local scan -> chunk sums
// (S_inc, S_mag, A = sum wc*cos(phi_local), B = sum wc*sin(phi_local))
// ---------------------------------------------------------------------------
__global__ void __launch_bounds__(Ddim)
passA_kernel(const float* __restrict__ x,
             const float* __restrict__ omega,
             const float* __restrict__ mag,
             const float* __restrict__ gate,
             const float* __restrict__ phii,
             const float* __restrict__ iscale,
             float4* __restrict__ csum)
{
    const int b = blockIdx.x / NC;
    const int c = blockIdx.x % NC;
    const int d = threadIdx.x;
    const float sc = fabsf(iscale[d]);
    size_t idx = ((size_t)b * Sdim + (size_t)c * CL) * Ddim + d;
    float rinc = 0.f, rmag = 0.f, rA = 0.f, rB = 0.f;
    #pragma unroll 4
    for (int s = 0; s < CL; s++, idx += Ddim) {
        float g = gate[idx], om = omega[idx], m = mag[idx];
        float xv = x[idx], pi = phii[idx];
        rinc += g * om * sc;
        float sp, cp;
        sincosf(pi + rinc, &sp, &cp);
        float wc = m * xv;
        rA += wc * cp;
        rB += wc * sp;
        rmag += m;
    }
    csum[(size_t)blockIdx.x * Ddim + d] = make_float4(rinc, rmag, rA, rB);
}

// ---------------------------------------------------------------------------
// Pass B: cross-chunk exclusive scan per (b,d) with trig rotation composition
// ---------------------------------------------------------------------------
__global__ void __launch_bounds__(Ddim)
passB_kernel(const float4* __restrict__ csum, float4* __restrict__ coff)
{
    const int b = blockIdx.x;
    const int d = threadIdx.x;
    float oi = 0.f, om = 0.f, omr = 0.f, omi = 0.f;
    #pragma unroll 4
    for (int c = 0; c < NC; c++) {
        const size_t i = ((size_t)b * NC + c) * Ddim + d;
        coff[i] = make_float4(oi, om, omr, omi);
        float4 s = csum[i];
        float st, ct;
        sincosf(oi, &st, &ct);
        omr += ct * s.z - st * s.w;
        omi += st * s.z + ct * s.w;
        oi += s.x;
        om += s.y;
    }
}

// ---------------------------------------------------------------------------
// Pass C: final scan + retrieval + fused LayerNorm over 4D=2048 (block-wide),
// writes normalized context [32768, 2048] ready for the W_o1 GEMM.
// Block = one (b, chunk); 512 threads = all d. For each s, the block holds
// all 2048 context values -> block reduction gives mean/var.
// ---------------------------------------------------------------------------
__global__ void __launch_bounds__(Ddim)
passC_kernel(const float* __restrict__ x,
             const float* __restrict__ omega,
             const float* __restrict__ mag,
             const float* __restrict__ gate,
             const float* __restrict__ phii,
             const float* __restrict__ qoffp,
             const float* __restrict__ iscale,
             const float* __restrict__ lng,
             const float* __restrict__ lnb,
             const float4* __restrict__ coff,
             float* __restrict__ ctx)
{
    __shared__ float2 warpred[16];
    __shared__ float2 bcast;
    const int b = blockIdx.x / NC;
    const int c = blockIdx.x % NC;
    const int d = threadIdx.x;
    const int lane = d & 31;
    const int wid = d >> 5;
    const float sc = fabsf(iscale[d]);
    const float g0 = lng[d],        g1 = lng[Ddim + d];
    const float g2 = lng[2*Ddim+d], g3 = lng[3*Ddim + d];
    const float l0 = lnb[d],        l1 = lnb[Ddim + d];
    const float l2 = lnb[2*Ddim+d], l3 = lnb[3*Ddim + d];

    float4 off = coff[(size_t)blockIdx.x * Ddim + d];
    float rinc = off.x, rmag = off.y, rmr = off.z, rmi = off.w;

    size_t idx   = ((size_t)b * Sdim + (size_t)c * CL) * Ddim + d;
    size_t cbase = ((size_t)b * Sdim + (size_t)c * CL) * (4 * Ddim) + d;

    for (int s = 0; s < CL; s++, idx += Ddim, cbase += 4 * Ddim) {
        float g = gate[idx], om = omega[idx], m = mag[idx];
        float xv = x[idx], pi = phii[idx], qo = qoffp[idx];
        rinc += g * om * sc;
        float phi = pi + rinc;
        float sp, cp;
        sincosf(phi, &sp, &cp);
        float wc = m * xv;
        rmr += wc * cp;
        rmi += wc * sp;
        rmag += m;
        float rq = rsqrtf(rmag + 1e-8f);
        float mrv = rmr * rq, miv = rmi * rq;
        float sq, cq;
        sincosf(phi + qo, &sq, &cq);
        float v0 = xv * cp, v1 = xv * sp;
        float v2 = mrv * cq + miv * sq;
        float v3 = miv * cq - mrv * sq;

        // LayerNorm reduction across the block (2048 values for this s)
        float lsum = v0 + v1 + v2 + v3;
        float lss  = v0 * v0 + v1 * v1 + v2 * v2 + v3 * v3;
        #pragma unroll
        for (int o = 16; o > 0; o >>= 1) {
            lsum += __shfl_down_sync(0xffffffffu, lsum, o);
            lss  += __shfl_down_sync(0xffffffffu, lss, o);
        }
        if (lane == 0) warpred[wid] = make_float2(lsum, lss);
        __syncthreads();
        if (wid == 0) {
            float2 t = (lane < 16) ? warpred[lane] : make_float2(0.f, 0.f);
            #pragma unroll
            for (int o = 8; o > 0; o >>= 1) {
                t.x += __shfl_down_sync(0xffffffffu, t.x, o);
                t.y += __shfl_down_sync(0xffffffffu, t.y, o);
            }
            if (lane == 0) bcast = t;
        }
        __syncthreads();
        const float mean = bcast.x * (1.0f / 2048.0f);
        const float var  = bcast.y * (1.0f / 2048.0f) - mean * mean;
        const float rstd = rsqrtf(var + 1e-5f);

        ctx[cbase           ] = (v0 - mean) * rstd * g0 + l0;
        ctx[cbase + Ddim    ] = (v1 - mean) * rstd * g1 + l1;
        ctx[cbase + 2 * Ddim] = (v2 - mean) * rstd * g2 + l2;
        ctx[cbase + 3 * Ddim] = (v3 - mean) * rstd * g3 + l3;
    }
}

// ---------------------------------------------------------------------------
// Launch
// ---------------------------------------------------------------------------
extern "C" void kernel_launch(void* const* d_in, const int* in_sizes, int n_in,
                              void* d_out, int out_size)
{
    const float* x       = (const float*)d_in[0];
    const float* W_omega = (const float*)d_in[1];
    const float* b_omega = (const float*)d_in[2];
    const float* W_p1    = (const float*)d_in[3];
    const float* b_p1    = (const float*)d_in[4];
    const float* W_p2    = (const float*)d_in[5];
    const float* b_p2    = (const float*)d_in[6];
    const float* W_gate  = (const float*)d_in[7];
    const float* b_gate  = (const float*)d_in[8];
    const float* iscale  = (const float*)d_in[9];
    const float* W_mag   = (const float*)d_in[10];
    const float* b_mag   = (const float*)d_in[11];
    const float* W_qoff  = (const float*)d_in[12];
    const float* b_qoff  = (const float*)d_in[13];
    const float* ln_g    = (const float*)d_in[14];
    const float* ln_b    = (const float*)d_in[15];
    const float* W_o1    = (const float*)d_in[16];
    const float* b_o1    = (const float*)d_in[17];
    const float* W_o2    = (const float*)d_in[18];
    const float* b_o2    = (const float*)d_in[19];
    float* out = (float*)d_out;

    float *p_omega, *p_mag, *p_gate, *p_qoff, *p_p1h, *p_phii, *p_ctx, *p_h;
    float4 *p_csum, *p_coff;
    cudaGetSymbolAddress((void**)&p_omega, g_omega);
    cudaGetSymbolAddress((void**)&p_mag,   g_mag);
    cudaGetSymbolAddress((void**)&p_gate,  g_gate);
    cudaGetSymbolAddress((void**)&p_qoff,  g_qoff);
    cudaGetSymbolAddress((void**)&p_p1h,   g_p1h);
    cudaGetSymbolAddress((void**)&p_phii,  g_phii);
    cudaGetSymbolAddress((void**)&p_ctx,   g_ctx);
    cudaGetSymbolAddress((void**)&p_h,     g_h);
    cudaGetSymbolAddress((void**)&p_csum,  g_csum);
    cudaGetSymbolAddress((void**)&p_coff,  g_coff);

    const dim3 blk(256);
    const dim3 gP(512 / 128, Mrows / 128);   // projections: N=512
    const dim3 gO1(1024 / 128, Mrows / 128); // W_o1: N=1024
    const dim3 gO2(512 / 128, Mrows / 128);  // W_o2: N=512

    // Projections
    sgemm_kernel<0><<<gP, blk>>>(x, W_omega, b_omega, nullptr, p_omega, Mrows, 512, 512);
    sgemm_kernel<2><<<gP, blk>>>(x, W_mag,   b_mag,   nullptr, p_mag,   Mrows, 512, 512);
    sgemm_kernel<1><<<gP, blk>>>(x, W_gate,  b_gate,  nullptr, p_gate,  Mrows, 512, 512);
    sgemm_kernel<0><<<gP, blk>>>(x, W_qoff,  b_qoff,  nullptr, p_qoff,  Mrows, 512, 512);
    sgemm_kernel<3><<<gP, blk>>>(x, W_p1,    b_p1,    nullptr, p_p1h,   Mrows, 512, 512);
    sgemm_kernel<0><<<gP, blk>>>(p_p1h, W_p2, b_p2,   nullptr, p_phii,  Mrows, 512, 512);

    // Decoupled sequence scan + fused LN context build
    passA_kernel<<<Bdim * NC, Ddim>>>(x, p_omega, p_mag, p_gate, p_phii, iscale, p_csum);
    passB_kernel<<<Bdim, Ddim>>>(p_csum, p_coff);
    passC_kernel<<<Bdim * NC, Ddim>>>(x, p_omega, p_mag, p_gate, p_phii, p_qoff,
                                      iscale, ln_g, ln_b, p_coff, p_ctx);

    // Output MLP
    sgemm_kernel<3><<<gO1, blk>>>(p_ctx, W_o1, b_o1, nullptr, p_h, Mrows, 1024, 2048);
    sgemm_kernel<4><<<gO2, blk>>>(p_h, W_o2, b_o2, x, out, Mrows, 512, 1024);
}

// round 4
// speedup vs baseline: 1.9467x; 1.9467x over previous
#include <cuda_runtime.h>
#include <cuda_bf16.h>
#include <math.h>
#include <stdint.h>

#define Bdim 8
#define Sdim 4096
#define Ddim 512
#define Mrows (Bdim * Sdim)
#define NC 32
#define CL (Sdim / NC)

// ---------------- scratch ----------------
__device__ float g_omega[(size_t)Mrows * Ddim];
__device__ float g_mag  [(size_t)Mrows * Ddim];
__device__ float g_gate [(size_t)Mrows * Ddim];
__device__ float g_qoff [(size_t)Mrows * Ddim];
__device__ float g_phii [(size_t)Mrows * Ddim];
__device__ __nv_bfloat16 g_xh [(size_t)Mrows * Ddim];
__device__ __nv_bfloat16 g_xl [(size_t)Mrows * Ddim];
__device__ __nv_bfloat16 g_p1h[(size_t)Mrows * Ddim];
__device__ __nv_bfloat16 g_p1l[(size_t)Mrows * Ddim];
__device__ __nv_bfloat16 g_cth[(size_t)Mrows * 4 * Ddim];
__device__ __nv_bfloat16 g_ctl[(size_t)Mrows * 4 * Ddim];
__device__ __nv_bfloat16 g_hh [(size_t)Mrows * 2 * Ddim];
__device__ __nv_bfloat16 g_hl [(size_t)Mrows * 2 * Ddim];
__device__ float4 g_csum[Bdim * NC * Ddim];
__device__ float4 g_coff[Bdim * NC * Ddim];
__device__ __nv_bfloat16 g_wh[4194304];
__device__ __nv_bfloat16 g_wl[4194304];

#define OFF_OM   0
#define OFF_MAG  262144
#define OFF_GATE 524288
#define OFF_QOFF 786432
#define OFF_P1   1048576
#define OFF_P2   1310720
#define OFF_O1   1572864
#define OFF_O2   3670016

// ---------------- helpers ----------------
__device__ __forceinline__ uint32_t smem_u32(const void* p) {
    uint32_t a;
    asm("{ .reg .u64 t; cvta.to.shared.u64 t, %1; cvt.u32.u64 %0, t; }" : "=r"(a) : "l"(p));
    return a;
}
#define CP16(so, gp) \
    asm volatile("cp.async.cg.shared.global [%0], [%1], 16;" :: "r"(so), "l"(gp) : "memory")
#define CP_COMMIT() asm volatile("cp.async.commit_group;" ::: "memory")
#define CP_WAIT1()  asm volatile("cp.async.wait_group 1;" ::: "memory")
#define CP_WAIT0()  asm volatile("cp.async.wait_group 0;" ::: "memory")

__device__ __forceinline__ void mma16816(float* c, const uint32_t* a, const uint32_t* b) {
    asm volatile(
        "mma.sync.aligned.m16n8k16.row.col.f32.bf16.bf16.f32 "
        "{%0,%1,%2,%3}, {%4,%5,%6,%7}, {%8,%9}, {%0,%1,%2,%3};"
        : "+f"(c[0]), "+f"(c[1]), "+f"(c[2]), "+f"(c[3])
        : "r"(a[0]), "r"(a[1]), "r"(a[2]), "r"(a[3]), "r"(b[0]), "r"(b[1]));
}

__device__ __forceinline__ float act_apply(float v, int ACT) {
    if (ACT == 1) return 1.0f / (1.0f + expf(-v));
    if (ACT == 2) return 5.0f / (1.0f + expf(-v));
    if (ACT == 3) return 0.5f * v * (1.0f + erff(v * 0.70710678118654752f));
    return v;
}

// W[K,N] fp32 -> Th/Tl[N,K] bf16 hi/lo
__global__ void wsplit_kernel(const float* __restrict__ W,
                              __nv_bfloat16* __restrict__ Th,
                              __nv_bfloat16* __restrict__ Tl,
                              int K, int N)
{
    __shared__ float t[32][33];
    const int tx = threadIdx.x, ty = threadIdx.y;
    const int n0 = blockIdx.x * 32, k0 = blockIdx.y * 32;
    #pragma unroll
    for (int i = 0; i < 32; i += 8)
        t[ty + i][tx] = W[(size_t)(k0 + ty + i) * N + n0 + tx];
    __syncthreads();
    #pragma unroll
    for (int i = 0; i < 32; i += 8) {
        const int n = n0 + ty + i, k = k0 + tx;
        float v = t[tx][ty + i];
        __nv_bfloat16 h = __float2bfloat16(v);
        Th[(size_t)n * K + k] = h;
        Tl[(size_t)n * K + k] = __float2bfloat16(v - __bfloat162float(h));
    }
}

// fp32 -> bf16 hi/lo split (for x)
__global__ void fsplit_kernel(const float* __restrict__ X,
                              __nv_bfloat16* __restrict__ H,
                              __nv_bfloat16* __restrict__ L)
{
    const size_t i = ((size_t)blockIdx.x * blockDim.x + threadIdx.x) * 4;
    float4 v = *(const float4*)(X + i);
    __nv_bfloat16 h0 = __float2bfloat16(v.x), h1 = __float2bfloat16(v.y);
    __nv_bfloat16 h2 = __float2bfloat16(v.z), h3 = __float2bfloat16(v.w);
    *(__nv_bfloat162*)(H + i)     = __nv_bfloat162(h0, h1);
    *(__nv_bfloat162*)(H + i + 2) = __nv_bfloat162(h2, h3);
    *(__nv_bfloat162*)(L + i)     = __nv_bfloat162(
        __float2bfloat16(v.x - __bfloat162float(h0)),
        __float2bfloat16(v.y - __bfloat162float(h1)));
    *(__nv_bfloat162*)(L + i + 2) = __nv_bfloat162(
        __float2bfloat16(v.z - __bfloat162float(h2)),
        __float2bfloat16(v.w - __bfloat162float(h3)));
}

// ---------------------------------------------------------------------------
// Split-bf16 HMMA GEMM: C = act(A @ W + bias) with A = Ah+Al, W = Wh+Wl
// CTA 128x128, BK=32, 256 thr, warp 64x32, cp.async double buffer.
// OUT: 0 = fp32 C   1 = bf16 hi/lo pair (Ch, Cl)
// ACT: 0 none, 1 sigmoid, 2 5*sigmoid, 3 gelu, 4 residual-add
// ---------------------------------------------------------------------------
#define SMEM_ELEMS 40960
#define SMEM_BYTES (SMEM_ELEMS * 2)

template <int ACT, int OUT>
__global__ void __launch_bounds__(256)
mma_gemm(const __nv_bfloat16* __restrict__ Ah, const __nv_bfloat16* __restrict__ Al,
         const __nv_bfloat16* __restrict__ Wh, const __nv_bfloat16* __restrict__ Wl,
         const float* __restrict__ bias, const float* __restrict__ resid,
         float* __restrict__ C,
         __nv_bfloat16* __restrict__ Ch, __nv_bfloat16* __restrict__ Cl,
         int K, int ldc)
{
    extern __shared__ __nv_bfloat16 sm[];
    const int tid = threadIdx.x;
    const int wid = tid >> 5, lane = tid & 31;
    const int wm = wid & 1, wn = wid >> 1;
    const int group = lane >> 2, qp = lane & 3;
    const int bn = blockIdx.x * 128, bm = blockIdx.y * 128;
    const uint32_t smb = smem_u32(sm);
    const int lrow = tid >> 2, lg = tid & 3;

    float acc[4][4][4];
    #pragma unroll
    for (int i = 0; i < 4; i++)
        #pragma unroll
        for (int j = 0; j < 4; j++)
            #pragma unroll
            for (int p = 0; p < 4; p++) acc[i][j][p] = 0.0f;

    const int NT = K >> 5;

#define LOADT(kt, st) do {                                                    \
    _Pragma("unroll")                                                         \
    for (int rep = 0; rep < 2; rep++) {                                       \
        const int row = lrow + rep * 64;                                      \
        const size_t ga = (size_t)(bm + row) * K + (kt) * 32 + lg * 8;        \
        const size_t gb = (size_t)(bn + row) * K + (kt) * 32 + lg * 8;        \
        const uint32_t so = smb + 2u * (uint32_t)((st) * 10240 + row * 40 + lg * 8); \
        CP16(so,              Ah + ga);                                       \
        CP16(so + 2 * 5120,   Al + ga);                                       \
        CP16(so + 2 * 20480,  Wh + gb);                                       \
        CP16(so + 2 * 25600,  Wl + gb);                                       \
    }                                                                         \
} while (0)

    LOADT(0, 0);
    CP_COMMIT();

    for (int kt = 0; kt < NT; kt++) {
        const int st = kt & 1;
        if (kt + 1 < NT) { LOADT(kt + 1, st ^ 1); CP_COMMIT(); CP_WAIT1(); }
        else CP_WAIT0();
        __syncthreads();

        const __nv_bfloat16* As = sm + st * 10240;
        const __nv_bfloat16* Bs = sm + 20480 + st * 10240;
        #pragma unroll
        for (int ks = 0; ks < 2; ks++) {
            const int kk = ks * 16 + qp * 2;
            uint32_t ah[4][4], al[4][4], bh[4][2], bl[4][2];
            #pragma unroll
            for (int i = 0; i < 4; i++) {
                const int r = wm * 64 + i * 16 + group;
                ah[i][0] = *(const uint32_t*)(As + r * 40 + kk);
                ah[i][1] = *(const uint32_t*)(As + (r + 8) * 40 + kk);
                ah[i][2] = *(const uint32_t*)(As + r * 40 + kk + 8);
                ah[i][3] = *(const uint32_t*)(As + (r + 8) * 40 + kk + 8);
                al[i][0] = *(const uint32_t*)(As + 5120 + r * 40 + kk);
                al[i][1] = *(const uint32_t*)(As + 5120 + (r + 8) * 40 + kk);
                al[i][2] = *(const uint32_t*)(As + 5120 + r * 40 + kk + 8);
                al[i][3] = *(const uint32_t*)(As + 5120 + (r + 8) * 40 + kk + 8);
            }
            #pragma unroll
            for (int j = 0; j < 4; j++) {
                const int n = wn * 32 + j * 8 + group;
                bh[j][0] = *(const uint32_t*)(Bs + n * 40 + kk);
                bh[j][1] = *(const uint32_t*)(Bs + n * 40 + kk + 8);
                bl[j][0] = *(const uint32_t*)(Bs + 5120 + n * 40 + kk);
                bl[j][1] = *(const uint32_t*)(Bs + 5120 + n * 40 + kk + 8);
            }
            #pragma unroll
            for (int i = 0; i < 4; i++)
                #pragma unroll
                for (int j = 0; j < 4; j++) {
                    mma16816(acc[i][j], ah[i], bh[j]);
                    mma16816(acc[i][j], al[i], bh[j]);
                    mma16816(acc[i][j], ah[i], bl[j]);
                }
        }
        __syncthreads();
    }

    // epilogue
    #pragma unroll
    for (int i = 0; i < 4; i++) {
        const int r0 = bm + wm * 64 + i * 16 + group;
        #pragma unroll
        for (int j = 0; j < 4; j++) {
            const int c = bn + wn * 32 + j * 8 + qp * 2;
            const float2 bb = *(const float2*)(bias + c);
            float v0 = acc[i][j][0] + bb.x;
            float v1 = acc[i][j][1] + bb.y;
            float v2 = acc[i][j][2] + bb.x;
            float v3 = acc[i][j][3] + bb.y;
            if (ACT == 4) {
                const float2 ra = *(const float2*)(resid + (size_t)r0 * ldc + c);
                const float2 rb = *(const float2*)(resid + (size_t)(r0 + 8) * ldc + c);
                v0 += ra.x; v1 += ra.y; v2 += rb.x; v3 += rb.y;
            } else {
                v0 = act_apply(v0, ACT); v1 = act_apply(v1, ACT);
                v2 = act_apply(v2, ACT); v3 = act_apply(v3, ACT);
            }
            if (OUT == 0) {
                *(float2*)(C + (size_t)r0 * ldc + c)       = make_float2(v0, v1);
                *(float2*)(C + (size_t)(r0 + 8) * ldc + c) = make_float2(v2, v3);
            } else {
                __nv_bfloat16 h0 = __float2bfloat16(v0), h1 = __float2bfloat16(v1);
                __nv_bfloat16 h2 = __float2bfloat16(v2), h3 = __float2bfloat16(v3);
                *(__nv_bfloat162*)(Ch + (size_t)r0 * ldc + c) = __nv_bfloat162(h0, h1);
                *(__nv_bfloat162*)(Ch + (size_t)(r0 + 8) * ldc + c) = __nv_bfloat162(h2, h3);
                *(__nv_bfloat162*)(Cl + (size_t)r0 * ldc + c) = __nv_bfloat162(
                    __float2bfloat16(v0 - __bfloat162float(h0)),
                    __float2bfloat16(v1 - __bfloat162float(h1)));
                *(__nv_bfloat162*)(Cl + (size_t)(r0 + 8) * ldc + c) = __nv_bfloat162(
                    __float2bfloat16(v2 - __bfloat162float(h2)),
                    __float2bfloat16(v3 - __bfloat162float(h3)));
            }
        }
    }
#undef LOADT
}

// ---------------- scan passes ----------------
__global__ void __launch_bounds__(Ddim)
passA_kernel(const float* __restrict__ x, const float* __restrict__ omega,
             const float* __restrict__ mag, const float* __restrict__ gate,
             const float* __restrict__ phii, const float* __restrict__ iscale,
             float4* __restrict__ csum)
{
    const int b = blockIdx.x / NC, c = blockIdx.x % NC, d = threadIdx.x;
    const float sc = fabsf(iscale[d]);
    size_t idx = ((size_t)b * Sdim + (size_t)c * CL) * Ddim + d;
    float rinc = 0.f, rmag = 0.f, rA = 0.f, rB = 0.f;
    #pragma unroll 4
    for (int s = 0; s < CL; s++, idx += Ddim) {
        float g = gate[idx], om = omega[idx], m = mag[idx];
        float xv = x[idx], pi = phii[idx];
        rinc += g * om * sc;
        float sp, cp;
        sincosf(pi + rinc, &sp, &cp);
        float wc = m * xv;
        rA += wc * cp; rB += wc * sp; rmag += m;
    }
    csum[(size_t)blockIdx.x * Ddim + d] = make_float4(rinc, rmag, rA, rB);
}

__global__ void __launch_bounds__(Ddim)
passB_kernel(const float4* __restrict__ csum, float4* __restrict__ coff)
{
    const int b = blockIdx.x, d = threadIdx.x;
    float oi = 0.f, om = 0.f, omr = 0.f, omi = 0.f;
    #pragma unroll 4
    for (int c = 0; c < NC; c++) {
        const size_t i = ((size_t)b * NC + c) * Ddim + d;
        coff[i] = make_float4(oi, om, omr, omi);
        float4 s = csum[i];
        float st, ct;
        sincosf(oi, &st, &ct);
        omr += ct * s.z - st * s.w;
        omi += st * s.z + ct * s.w;
        oi += s.x; om += s.y;
    }
}

__global__ void __launch_bounds__(Ddim)
passC_kernel(const float* __restrict__ x, const float* __restrict__ omega,
             const float* __restrict__ mag, const float* __restrict__ gate,
             const float* __restrict__ phii, const float* __restrict__ qoffp,
             const float* __restrict__ iscale, const float* __restrict__ lng,
             const float* __restrict__ lnb, const float4* __restrict__ coff,
             __nv_bfloat16* __restrict__ cth, __nv_bfloat16* __restrict__ ctl)
{
    __shared__ float2 warpred[16];
    __shared__ float2 bcast;
    const int b = blockIdx.x / NC, c = blockIdx.x % NC, d = threadIdx.x;
    const int lane = d & 31, wid = d >> 5;
    const float sc = fabsf(iscale[d]);
    const float g0 = lng[d], g1 = lng[Ddim + d], g2 = lng[2*Ddim+d], g3 = lng[3*Ddim+d];
    const float l0 = lnb[d], l1 = lnb[Ddim + d], l2 = lnb[2*Ddim+d], l3 = lnb[3*Ddim+d];

    float4 off = coff[(size_t)blockIdx.x * Ddim + d];
    float rinc = off.x, rmag = off.y, rmr = off.z, rmi = off.w;
    size_t idx   = ((size_t)b * Sdim + (size_t)c * CL) * Ddim + d;
    size_t cbase = ((size_t)b * Sdim + (size_t)c * CL) * (4 * Ddim) + d;

    for (int s = 0; s < CL; s++, idx += Ddim, cbase += 4 * Ddim) {
        float g = gate[idx], om = omega[idx], m = mag[idx];
        float xv = x[idx], pi = phii[idx], qo = qoffp[idx];
        rinc += g * om * sc;
        float phi = pi + rinc;
        float sp, cp;
        sincosf(phi, &sp, &cp);
        float wc = m * xv;
        rmr += wc * cp; rmi += wc * sp; rmag += m;
        float rq = rsqrtf(rmag + 1e-8f);
        float mrv = rmr * rq, miv = rmi * rq;
        float sq, cq;
        sincosf(phi + qo, &sq, &cq);
        float v0 = xv * cp, v1 = xv * sp;
        float v2 = mrv * cq + miv * sq;
        float v3 = miv * cq - mrv * sq;

        float lsum = v0 + v1 + v2 + v3;
        float lss  = v0 * v0 + v1 * v1 + v2 * v2 + v3 * v3;
        #pragma unroll
        for (int o = 16; o > 0; o >>= 1) {
            lsum += __shfl_down_sync(0xffffffffu, lsum, o);
            lss  += __shfl_down_sync(0xffffffffu, lss, o);
        }
        if (lane == 0) warpred[wid] = make_float2(lsum, lss);
        __syncthreads();
        if (wid == 0) {
            float2 t = (lane < 16) ? warpred[lane] : make_float2(0.f, 0.f);
            #pragma unroll
            for (int o = 8; o > 0; o >>= 1) {
                t.x += __shfl_down_sync(0xffffffffu, t.x, o);
                t.y += __shfl_down_sync(0xffffffffu, t.y, o);
            }
            if (lane == 0) bcast = t;
        }
        __syncthreads();
        const float mean = bcast.x * (1.0f / 2048.0f);
        const float var  = bcast.y * (1.0f / 2048.0f) - mean * mean;
        const float rstd = rsqrtf(var + 1e-5f);
        float y0 = (v0 - mean) * rstd * g0 + l0;
        float y1 = (v1 - mean) * rstd * g1 + l1;
        float y2 = (v2 - mean) * rstd * g2 + l2;
        float y3 = (v3 - mean) * rstd * g3 + l3;
        #pragma unroll
        for (int q = 0; q < 4; q++) {
            float yv = (q == 0) ? y0 : (q == 1) ? y1 : (q == 2) ? y2 : y3;
            __nv_bfloat16 hh = __float2bfloat16(yv);
            cth[cbase + q * Ddim] = hh;
            ctl[cbase + q * Ddim] = __float2bfloat16(yv - __bfloat162float(hh));
        }
    }
}

// ---------------- launch ----------------
extern "C" void kernel_launch(void* const* d_in, const int* in_sizes, int n_in,
                              void* d_out, int out_size)
{
    const float* x       = (const float*)d_in[0];
    const float* W_omega = (const float*)d_in[1];
    const float* b_omega = (const float*)d_in[2];
    const float* W_p1    = (const float*)d_in[3];
    const float* b_p1    = (const float*)d_in[4];
    const float* W_p2    = (const float*)d_in[5];
    const float* b_p2    = (const float*)d_in[6];
    const float* W_gate  = (const float*)d_in[7];
    const float* b_gate  = (const float*)d_in[8];
    const float* iscale  = (const float*)d_in[9];
    const float* W_mag   = (const float*)d_in[10];
    const float* b_mag   = (const float*)d_in[11];
    const float* W_qoff  = (const float*)d_in[12];
    const float* b_qoff  = (const float*)d_in[13];
    const float* ln_g    = (const float*)d_in[14];
    const float* ln_b    = (const float*)d_in[15];
    const float* W_o1    = (const float*)d_in[16];
    const float* b_o1    = (const float*)d_in[17];
    const float* W_o2    = (const float*)d_in[18];
    const float* b_o2    = (const float*)d_in[19];
    float* out = (float*)d_out;

    float *p_omega, *p_mag, *p_gate, *p_qoff, *p_phii;
    __nv_bfloat16 *p_xh, *p_xl, *p_p1h, *p_p1l, *p_cth, *p_ctl, *p_hh, *p_hl, *p_wh, *p_wl;
    float4 *p_csum, *p_coff;
    cudaGetSymbolAddress((void**)&p_omega, g_omega);
    cudaGetSymbolAddress((void**)&p_mag,   g_mag);
    cudaGetSymbolAddress((void**)&p_gate,  g_gate);
    cudaGetSymbolAddress((void**)&p_qoff,  g_qoff);
    cudaGetSymbolAddress((void**)&p_phii,  g_phii);
    cudaGetSymbolAddress((void**)&p_xh,    g_xh);
    cudaGetSymbolAddress((void**)&p_xl,    g_xl);
    cudaGetSymbolAddress((void**)&p_p1h,   g_p1h);
    cudaGetSymbolAddress((void**)&p_p1l,   g_p1l);
    cudaGetSymbolAddress((void**)&p_cth,   g_cth);
    cudaGetSymbolAddress((void**)&p_ctl,   g_ctl);
    cudaGetSymbolAddress((void**)&p_hh,    g_hh);
    cudaGetSymbolAddress((void**)&p_hl,    g_hl);
    cudaGetSymbolAddress((void**)&p_wh,    g_wh);
    cudaGetSymbolAddress((void**)&p_wl,    g_wl);
    cudaGetSymbolAddress((void**)&p_csum,  g_csum);
    cudaGetSymbolAddress((void**)&p_coff,  g_coff);

    cudaFuncSetAttribute(mma_gemm<0,0>, cudaFuncAttributeMaxDynamicSharedMemorySize, SMEM_BYTES);
    cudaFuncSetAttribute(mma_gemm<1,0>, cudaFuncAttributeMaxDynamicSharedMemorySize, SMEM_BYTES);
    cudaFuncSetAttribute(mma_gemm<2,0>, cudaFuncAttributeMaxDynamicSharedMemorySize, SMEM_BYTES);
    cudaFuncSetAttribute(mma_gemm<3,1>, cudaFuncAttributeMaxDynamicSharedMemorySize, SMEM_BYTES);
    cudaFuncSetAttribute(mma_gemm<4,0>, cudaFuncAttributeMaxDynamicSharedMemorySize, SMEM_BYTES);

    const dim3 tb(32, 8);
    wsplit_kernel<<<dim3(16, 16), tb>>>(W_omega, p_wh + OFF_OM,   p_wl + OFF_OM,   512, 512);
    wsplit_kernel<<<dim3(16, 16), tb>>>(W_mag,   p_wh + OFF_MAG,  p_wl + OFF_MAG,  512, 512);
    wsplit_kernel<<<dim3(16, 16), tb>>>(W_gate,  p_wh + OFF_GATE, p_wl + OFF_GATE, 512, 512);
    wsplit_kernel<<<dim3(16, 16), tb>>>(W_qoff,  p_wh + OFF_QOFF, p_wl + OFF_QOFF, 512, 512);
    wsplit_kernel<<<dim3(16, 16), tb>>>(W_p1,    p_wh + OFF_P1,   p_wl + OFF_P1,   512, 512);
    wsplit_kernel<<<dim3(16, 16), tb>>>(W_p2,    p_wh + OFF_P2,   p_wl + OFF_P2,   512, 512);
    wsplit_kernel<<<dim3(32, 64), tb>>>(W_o1,    p_wh + OFF_O1,   p_wl + OFF_O1,   2048, 1024);
    wsplit_kernel<<<dim3(16, 32), tb>>>(W_o2,    p_wh + OFF_O2,   p_wl + OFF_O2,   1024, 512);

    fsplit_kernel<<<(size_t)Mrows * Ddim / 4 / 256, 256>>>(x, p_xh, p_xl);

    const dim3 blk(256);
    const dim3 gP(4, Mrows / 128);
    const dim3 gO1(8, Mrows / 128);
    const dim3 gO2(4, Mrows / 128);

    mma_gemm<0,0><<<gP, blk, SMEM_BYTES>>>(p_xh, p_xl, p_wh + OFF_OM,   p_wl + OFF_OM,   b_omega, 0, p_omega, 0, 0, 512, 512);
    mma_gemm<2,0><<<gP, blk, SMEM_BYTES>>>(p_xh, p_xl, p_wh + OFF_MAG,  p_wl + OFF_MAG,  b_mag,   0, p_mag,   0, 0, 512, 512);
    mma_gemm<1,0><<<gP, blk, SMEM_BYTES>>>(p_xh, p_xl, p_wh + OFF_GATE, p_wl + OFF_GATE, b_gate,  0, p_gate,  0, 0, 512, 512);
    mma_gemm<0,0><<<gP, blk, SMEM_BYTES>>>(p_xh, p_xl, p_wh + OFF_QOFF, p_wl + OFF_QOFF, b_qoff,  0, p_qoff,  0, 0, 512, 512);
    mma_gemm<3,1><<<gP, blk, SMEM_BYTES>>>(p_xh, p_xl, p_wh + OFF_P1,   p_wl + OFF_P1,   b_p1,    0, 0, p_p1h, p_p1l, 512, 512);
    mma_gemm<0,0><<<gP, blk, SMEM_BYTES>>>(p_p1h, p_p1l, p_wh + OFF_P2, p_wl + OFF_P2,   b_p2,    0, p_phii, 0, 0, 512, 512);

    passA_kernel<<<Bdim * NC, Ddim>>>(x, p_omega, p_mag, p_gate, p_phii, iscale, p_csum);
    passB_kernel<<<Bdim, Ddim>>>(p_csum, p_coff);
    passC_kernel<<<Bdim * NC, Ddim>>>(x, p_omega, p_mag, p_gate, p_phii, p_qoff,
                                      iscale, ln_g, ln_b, p_coff, p_cth, p_ctl);

    mma_gemm<3,1><<<gO1, blk, SMEM_BYTES>>>(p_cth, p_ctl, p_wh + OFF_O1, p_wl + OFF_O1, b_o1, 0, 0, p_hh, p_hl, 2048, 1024);
    mma_gemm<4,0><<<gO2, blk, SMEM_BYTES>>>(p_hh, p_hl, p_wh + OFF_O2, p_wl + OFF_O2, b_o2, x, out, 0, 0, 1024, 512);
}

// round 5
// speedup vs baseline: 4.2395x; 2.1778x over previous
#include <cuda_runtime.h>
#include <cuda_fp16.h>
#include <math.h>
#include <stdint.h>

#define Bdim 8
#define Sdim 4096
#define Ddim 512
#define Mrows (Bdim * Sdim)
#define NC 32
#define CL (Sdim / NC)

// ---------------- scratch ----------------
__device__ float g_omega[(size_t)Mrows * Ddim];
__device__ float g_mag  [(size_t)Mrows * Ddim];
__device__ float g_gate [(size_t)Mrows * Ddim];
__device__ float g_qoff [(size_t)Mrows * Ddim];
__device__ float g_phii [(size_t)Mrows * Ddim];
__device__ __half g_xf  [(size_t)Mrows * Ddim];
__device__ __half g_p1f [(size_t)Mrows * Ddim];
__device__ __half g_ctxf[(size_t)Mrows * 4 * Ddim];
__device__ __half g_hf  [(size_t)Mrows * 2 * Ddim];
__device__ float4 g_csum[Bdim * NC * Ddim];
__device__ float4 g_coff[Bdim * NC * Ddim];
__device__ __half g_wf[4194304];

#define OFF_OM   0
#define OFF_MAG  262144
#define OFF_GATE 524288
#define OFF_QOFF 786432
#define OFF_P1   1048576
#define OFF_P2   1310720
#define OFF_O1   1572864
#define OFF_O2   3670016

// ---------------- helpers ----------------
__device__ __forceinline__ uint32_t smem_u32(const void* p) {
    uint32_t a;
    asm("{ .reg .u64 t; cvta.to.shared.u64 t, %1; cvt.u32.u64 %0, t; }" : "=r"(a) : "l"(p));
    return a;
}
#define CP16(so, gp) \
    asm volatile("cp.async.cg.shared.global [%0], [%1], 16;" :: "r"(so), "l"(gp) : "memory")
#define CP_COMMIT() asm volatile("cp.async.commit_group;" ::: "memory")
#define CP_WAIT1()  asm volatile("cp.async.wait_group 1;" ::: "memory")
#define CP_WAIT0()  asm volatile("cp.async.wait_group 0;" ::: "memory")

#define LDSM4(r0, r1, r2, r3, a)                                              \
    asm volatile("ldmatrix.sync.aligned.m8n8.x4.shared.b16 {%0,%1,%2,%3}, [%4];" \
                 : "=r"(r0), "=r"(r1), "=r"(r2), "=r"(r3) : "r"(a))

__device__ __forceinline__ void mma16816(float* c, const uint32_t* a, const uint32_t* b) {
    asm volatile(
        "mma.sync.aligned.m16n8k16.row.col.f32.f16.f16.f32 "
        "{%0,%1,%2,%3}, {%4,%5,%6,%7}, {%8,%9}, {%0,%1,%2,%3};"
        : "+f"(c[0]), "+f"(c[1]), "+f"(c[2]), "+f"(c[3])
        : "r"(a[0]), "r"(a[1]), "r"(a[2]), "r"(a[3]), "r"(b[0]), "r"(b[1]));
}

__device__ __forceinline__ float act_apply(float v, int ACT) {
    if (ACT == 1) return 1.0f / (1.0f + expf(-v));
    if (ACT == 2) return 5.0f / (1.0f + expf(-v));
    if (ACT == 3) return 0.5f * v * (1.0f + erff(v * 0.70710678118654752f));
    return v;
}

// W[K,N] fp32 -> T[N,K] fp16 (transpose + convert)
__global__ void wconv_kernel(const float* __restrict__ W, __half* __restrict__ T,
                             int K, int N)
{
    __shared__ float t[32][33];
    const int tx = threadIdx.x, ty = threadIdx.y;
    const int n0 = blockIdx.x * 32, k0 = blockIdx.y * 32;
    #pragma unroll
    for (int i = 0; i < 32; i += 8)
        t[ty + i][tx] = W[(size_t)(k0 + ty + i) * N + n0 + tx];
    __syncthreads();
    #pragma unroll
    for (int i = 0; i < 32; i += 8)
        T[(size_t)(n0 + ty + i) * K + k0 + tx] = __float2half(t[tx][ty + i]);
}

// fp32 -> fp16
__global__ void fconv_kernel(const float* __restrict__ X, __half* __restrict__ H)
{
    const size_t i = ((size_t)blockIdx.x * blockDim.x + threadIdx.x) * 4;
    float4 v = *(const float4*)(X + i);
    *(__half2*)(H + i)     = __floats2half2_rn(v.x, v.y);
    *(__half2*)(H + i + 2) = __floats2half2_rn(v.z, v.w);
}

// ---------------------------------------------------------------------------
// fp16 HMMA GEMM: C = act(A[M,K] @ W + bias) (+resid)
// CTA 128x128, BK=32, 256 thr, warp 64x32, 3-stage cp.async, ldmatrix frags.
// OUT: 0 = fp32 C,  1 = fp16 C.   ACT: 0 none,1 sig,2 5sig,3 gelu,4 resid.
// smem rows padded to 40 halfs (80B) -> conflict-free ldmatrix + cp.async.
// ---------------------------------------------------------------------------
#define STG_ELEMS 10240
#define SMEM_BYTES (3 * STG_ELEMS * 2)

template <int ACT, int OUT>
__global__ void __launch_bounds__(256)
mma_gemm(const __half* __restrict__ A, const __half* __restrict__ W,
         const float* __restrict__ bias, const float* __restrict__ resid,
         float* __restrict__ C, __half* __restrict__ Cf,
         int K, int ldc)
{
    extern __shared__ __half sm[];
    const int tid = threadIdx.x;
    const int wid = tid >> 5, lane = tid & 31;
    const int wm = wid & 1, wn = wid >> 1;
    const int group = lane >> 2, qp = lane & 3;
    const int bn = blockIdx.x * 128, bm = blockIdx.y * 128;
    const uint32_t smb = smem_u32(sm);
    const int lrow = tid >> 2, lg = tid & 3;

    // ldmatrix per-lane element offsets (within a 16x16 / 16(n)x16(k) tile)
    const uint32_t offA = (uint32_t)((lane & 7) * 40 + ((lane >> 3) & 1) * 320 + (lane >> 4) * 8);
    const uint32_t offB = (uint32_t)((lane & 7) * 40 + ((lane >> 3) & 1) * 8 + (lane >> 4) * 320);

    float acc[4][4][4];
    #pragma unroll
    for (int i = 0; i < 4; i++)
        #pragma unroll
        for (int j = 0; j < 4; j++)
            #pragma unroll
            for (int p = 0; p < 4; p++) acc[i][j][p] = 0.0f;

    const int NT = K >> 5;

#define LOADT(kt, st) do {                                                    \
    _Pragma("unroll")                                                         \
    for (int rep = 0; rep < 2; rep++) {                                       \
        const int row = lrow + rep * 64;                                      \
        const size_t ga = (size_t)(bm + row) * K + (size_t)(kt) * 32 + lg * 8; \
        const size_t gb = (size_t)(bn + row) * K + (size_t)(kt) * 32 + lg * 8; \
        const uint32_t so = smb + 2u * (uint32_t)((st) * STG_ELEMS + row * 40 + lg * 8); \
        CP16(so, A + ga);                                                     \
        CP16(so + 2 * 5120, W + gb);                                          \
    }                                                                         \
} while (0)

    LOADT(0, 0); CP_COMMIT();
    if (NT > 1) { LOADT(1, 1); CP_COMMIT(); }

    for (int kt = 0; kt < NT; kt++) {
        const int st = kt % 3;
        if (kt + 1 < NT) CP_WAIT1(); else CP_WAIT0();
        __syncthreads();
        if (kt + 2 < NT) { LOADT(kt + 2, (kt + 2) % 3); CP_COMMIT(); }

        const uint32_t As = smb + 2u * (uint32_t)(st * STG_ELEMS);
        const uint32_t Bs = As + 2u * 5120u;
        #pragma unroll
        for (int ks = 0; ks < 2; ks++) {
            uint32_t ah[4][4], bb[2][4];
            #pragma unroll
            for (int i = 0; i < 4; i++) {
                const uint32_t ad = As + 2u * (uint32_t)((wm * 64 + i * 16) * 40 + ks * 16) + 2u * offA;
                LDSM4(ah[i][0], ah[i][1], ah[i][2], ah[i][3], ad);
            }
            #pragma unroll
            for (int jj = 0; jj < 2; jj++) {
                const uint32_t bd = Bs + 2u * (uint32_t)((wn * 32 + jj * 16) * 40 + ks * 16) + 2u * offB;
                LDSM4(bb[jj][0], bb[jj][1], bb[jj][2], bb[jj][3], bd);
            }
            #pragma unroll
            for (int i = 0; i < 4; i++)
                #pragma unroll
                for (int j = 0; j < 4; j++)
                    mma16816(acc[i][j], ah[i], &bb[j >> 1][(j & 1) * 2]);
        }
        __syncthreads();
    }

    // epilogue
    #pragma unroll
    for (int i = 0; i < 4; i++) {
        const int r0 = bm + wm * 64 + i * 16 + group;
        #pragma unroll
        for (int j = 0; j < 4; j++) {
            const int c = bn + wn * 32 + j * 8 + qp * 2;
            const float2 bv = *(const float2*)(bias + c);
            float v0 = acc[i][j][0] + bv.x;
            float v1 = acc[i][j][1] + bv.y;
            float v2 = acc[i][j][2] + bv.x;
            float v3 = acc[i][j][3] + bv.y;
            if (ACT == 4) {
                const float2 ra = *(const float2*)(resid + (size_t)r0 * ldc + c);
                const float2 rb = *(const float2*)(resid + (size_t)(r0 + 8) * ldc + c);
                v0 += ra.x; v1 += ra.y; v2 += rb.x; v3 += rb.y;
            } else {
                v0 = act_apply(v0, ACT); v1 = act_apply(v1, ACT);
                v2 = act_apply(v2, ACT); v3 = act_apply(v3, ACT);
            }
            if (OUT == 0) {
                *(float2*)(C + (size_t)r0 * ldc + c)       = make_float2(v0, v1);
                *(float2*)(C + (size_t)(r0 + 8) * ldc + c) = make_float2(v2, v3);
            } else {
                *(__half2*)(Cf + (size_t)r0 * ldc + c)       = __floats2half2_rn(v0, v1);
                *(__half2*)(Cf + (size_t)(r0 + 8) * ldc + c) = __floats2half2_rn(v2, v3);
            }
        }
    }
#undef LOADT
}

// ---------------- scan passes ----------------
__global__ void __launch_bounds__(Ddim)
passA_kernel(const float* __restrict__ x, const float* __restrict__ omega,
             const float* __restrict__ mag, const float* __restrict__ gate,
             const float* __restrict__ phii, const float* __restrict__ iscale,
             float4* __restrict__ csum)
{
    const int b = blockIdx.x / NC, c = blockIdx.x % NC, d = threadIdx.x;
    const float sc = fabsf(iscale[d]);
    size_t idx = ((size_t)b * Sdim + (size_t)c * CL) * Ddim + d;
    float rinc = 0.f, rmag = 0.f, rA = 0.f, rB = 0.f;
    #pragma unroll 4
    for (int s = 0; s < CL; s++, idx += Ddim) {
        float g = gate[idx], om = omega[idx], m = mag[idx];
        float xv = x[idx], pi = phii[idx];
        rinc += g * om * sc;
        float sp, cp;
        sincosf(pi + rinc, &sp, &cp);
        float wc = m * xv;
        rA += wc * cp; rB += wc * sp; rmag += m;
    }
    csum[(size_t)blockIdx.x * Ddim + d] = make_float4(rinc, rmag, rA, rB);
}

__global__ void __launch_bounds__(Ddim)
passB_kernel(const float4* __restrict__ csum, float4* __restrict__ coff)
{
    const int b = blockIdx.x, d = threadIdx.x;
    float oi = 0.f, om = 0.f, omr = 0.f, omi = 0.f;
    #pragma unroll 4
    for (int c = 0; c < NC; c++) {
        const size_t i = ((size_t)b * NC + c) * Ddim + d;
        coff[i] = make_float4(oi, om, omr, omi);
        float4 s = csum[i];
        float st, ct;
        sincosf(oi, &st, &ct);
        omr += ct * s.z - st * s.w;
        omi += st * s.z + ct * s.w;
        oi += s.x; om += s.y;
    }
}

__global__ void __launch_bounds__(Ddim)
passC_kernel(const float* __restrict__ x, const float* __restrict__ omega,
             const float* __restrict__ mag, const float* __restrict__ gate,
             const float* __restrict__ phii, const float* __restrict__ qoffp,
             const float* __restrict__ iscale, const float* __restrict__ lng,
             const float* __restrict__ lnb, const float4* __restrict__ coff,
             __half* __restrict__ ctx)
{
    __shared__ float2 warpred[16];
    __shared__ float2 bcast;
    const int b = blockIdx.x / NC, c = blockIdx.x % NC, d = threadIdx.x;
    const int lane = d & 31, wid = d >> 5;
    const float sc = fabsf(iscale[d]);
    const float g0 = lng[d], g1 = lng[Ddim + d], g2 = lng[2*Ddim+d], g3 = lng[3*Ddim+d];
    const float l0 = lnb[d], l1 = lnb[Ddim + d], l2 = lnb[2*Ddim+d], l3 = lnb[3*Ddim+d];

    float4 off = coff[(size_t)blockIdx.x * Ddim + d];
    float rinc = off.x, rmag = off.y, rmr = off.z, rmi = off.w;
    size_t idx   = ((size_t)b * Sdim + (size_t)c * CL) * Ddim + d;
    size_t cbase = ((size_t)b * Sdim + (size_t)c * CL) * (4 * Ddim) + d;

    for (int s = 0; s < CL; s++, idx += Ddim, cbase += 4 * Ddim) {
        float g = gate[idx], om = omega[idx], m = mag[idx];
        float xv = x[idx], pi = phii[idx], qo = qoffp[idx];
        rinc += g * om * sc;
        float phi = pi + rinc;
        float sp, cp;
        sincosf(phi, &sp, &cp);
        float wc = m * xv;
        rmr += wc * cp; rmi += wc * sp; rmag += m;
        float rq = rsqrtf(rmag + 1e-8f);
        float mrv = rmr * rq, miv = rmi * rq;
        float sq, cq;
        sincosf(phi + qo, &sq, &cq);
        float v0 = xv * cp, v1 = xv * sp;
        float v2 = mrv * cq + miv * sq;
        float v3 = miv * cq - mrv * sq;

        float lsum = v0 + v1 + v2 + v3;
        float lss  = v0 * v0 + v1 * v1 + v2 * v2 + v3 * v3;
        #pragma unroll
        for (int o = 16; o > 0; o >>= 1) {
            lsum += __shfl_down_sync(0xffffffffu, lsum, o);
            lss  += __shfl_down_sync(0xffffffffu, lss, o);
        }
        if (lane == 0) warpred[wid] = make_float2(lsum, lss);
        __syncthreads();
        if (wid == 0) {
            float2 t = (lane < 16) ? warpred[lane] : make_float2(0.f, 0.f);
            #pragma unroll
            for (int o = 8; o > 0; o >>= 1) {
                t.x += __shfl_down_sync(0xffffffffu, t.x, o);
                t.y += __shfl_down_sync(0xffffffffu, t.y, o);
            }
            if (lane == 0) bcast = t;
        }
        __syncthreads();
        const float mean = bcast.x * (1.0f / 2048.0f);
        const float var  = bcast.y * (1.0f / 2048.0f) - mean * mean;
        const float rstd = rsqrtf(var + 1e-5f);
        ctx[cbase           ] = __float2half((v0 - mean) * rstd * g0 + l0);
        ctx[cbase + Ddim    ] = __float2half((v1 - mean) * rstd * g1 + l1);
        ctx[cbase + 2 * Ddim] = __float2half((v2 - mean) * rstd * g2 + l2);
        ctx[cbase + 3 * Ddim] = __float2half((v3 - mean) * rstd * g3 + l3);
    }
}

// ---------------- launch ----------------
extern "C" void kernel_launch(void* const* d_in, const int* in_sizes, int n_in,
                              void* d_out, int out_size)
{
    const float* x       = (const float*)d_in[0];
    const float* W_omega = (const float*)d_in[1];
    const float* b_omega = (const float*)d_in[2];
    const float* W_p1    = (const float*)d_in[3];
    const float* b_p1    = (const float*)d_in[4];
    const float* W_p2    = (const float*)d_in[5];
    const float* b_p2    = (const float*)d_in[6];
    const float* W_gate  = (const float*)d_in[7];
    const float* b_gate  = (const float*)d_in[8];
    const float* iscale  = (const float*)d_in[9];
    const float* W_mag   = (const float*)d_in[10];
    const float* b_mag   = (const float*)d_in[11];
    const float* W_qoff  = (const float*)d_in[12];
    const float* b_qoff  = (const float*)d_in[13];
    const float* ln_g    = (const float*)d_in[14];
    const float* ln_b    = (const float*)d_in[15];
    const float* W_o1    = (const float*)d_in[16];
    const float* b_o1    = (const float*)d_in[17];
    const float* W_o2    = (const float*)d_in[18];
    const float* b_o2    = (const float*)d_in[19];
    float* out = (float*)d_out;

    float *p_omega, *p_mag, *p_gate, *p_qoff, *p_phii;
    __half *p_xf, *p_p1f, *p_ctxf, *p_hf, *p_wf;
    float4 *p_csum, *p_coff;
    cudaGetSymbolAddress((void**)&p_omega, g_omega);
    cudaGetSymbolAddress((void**)&p_mag,   g_mag);
    cudaGetSymbolAddress((void**)&p_gate,  g_gate);
    cudaGetSymbolAddress((void**)&p_qoff,  g_qoff);
    cudaGetSymbolAddress((void**)&p_phii,  g_phii);
    cudaGetSymbolAddress((void**)&p_xf,    g_xf);
    cudaGetSymbolAddress((void**)&p_p1f,   g_p1f);
    cudaGetSymbolAddress((void**)&p_ctxf,  g_ctxf);
    cudaGetSymbolAddress((void**)&p_hf,    g_hf);
    cudaGetSymbolAddress((void**)&p_wf,    g_wf);
    cudaGetSymbolAddress((void**)&p_csum,  g_csum);
    cudaGetSymbolAddress((void**)&p_coff,  g_coff);

    cudaFuncSetAttribute(mma_gemm<0,0>, cudaFuncAttributeMaxDynamicSharedMemorySize, SMEM_BYTES);
    cudaFuncSetAttribute(mma_gemm<1,0>, cudaFuncAttributeMaxDynamicSharedMemorySize, SMEM_BYTES);
    cudaFuncSetAttribute(mma_gemm<2,0>, cudaFuncAttributeMaxDynamicSharedMemorySize, SMEM_BYTES);
    cudaFuncSetAttribute(mma_gemm<3,1>, cudaFuncAttributeMaxDynamicSharedMemorySize, SMEM_BYTES);
    cudaFuncSetAttribute(mma_gemm<4,0>, cudaFuncAttributeMaxDynamicSharedMemorySize, SMEM_BYTES);

    const dim3 tb(32, 8);
    wconv_kernel<<<dim3(16, 16), tb>>>(W_omega, p_wf + OFF_OM,   512, 512);
    wconv_kernel<<<dim3(16, 16), tb>>>(W_mag,   p_wf + OFF_MAG,  512, 512);
    wconv_kernel<<<dim3(16, 16), tb>>>(W_gate,  p_wf + OFF_GATE, 512, 512);
    wconv_kernel<<<dim3(16, 16), tb>>>(W_qoff,  p_wf + OFF_QOFF, 512, 512);
    wconv_kernel<<<dim3(16, 16), tb>>>(W_p1,    p_wf + OFF_P1,   512, 512);
    wconv_kernel<<<dim3(16, 16), tb>>>(W_p2,    p_wf + OFF_P2,   512, 512);
    wconv_kernel<<<dim3(32, 64), tb>>>(W_o1,    p_wf + OFF_O1,   2048, 1024);
    wconv_kernel<<<dim3(16, 32), tb>>>(W_o2,    p_wf + OFF_O2,   1024, 512);

    fconv_kernel<<<(size_t)Mrows * Ddim / 4 / 256, 256>>>(x, p_xf);

    const dim3 blk(256);
    const dim3 gP(4, Mrows / 128);
    const dim3 gO1(8, Mrows / 128);
    const dim3 gO2(4, Mrows / 128);

    mma_gemm<0,0><<<gP, blk, SMEM_BYTES>>>(p_xf, p_wf + OFF_OM,   b_omega, 0, p_omega, 0, 512, 512);
    mma_gemm<2,0><<<gP, blk, SMEM_BYTES>>>(p_xf, p_wf + OFF_MAG,  b_mag,   0, p_mag,   0, 512, 512);
    mma_gemm<1,0><<<gP, blk, SMEM_BYTES>>>(p_xf, p_wf + OFF_GATE, b_gate,  0, p_gate,  0, 512, 512);
    mma_gemm<0,0><<<gP, blk, SMEM_BYTES>>>(p_xf, p_wf + OFF_QOFF, b_qoff,  0, p_qoff,  0, 512, 512);
    mma_gemm<3,1><<<gP, blk, SMEM_BYTES>>>(p_xf, p_wf + OFF_P1,   b_p1,    0, 0, p_p1f, 512, 512);
    mma_gemm<0,0><<<gP, blk, SMEM_BYTES>>>(p_p1f, p_wf + OFF_P2,  b_p2,    0, p_phii,  0, 512, 512);

    passA_kernel<<<Bdim * NC, Ddim>>>(x, p_omega, p_mag, p_gate, p_phii, iscale, p_csum);
    passB_kernel<<<Bdim, Ddim>>>(p_csum, p_coff);
    passC_kernel<<<Bdim * NC, Ddim>>>(x, p_omega, p_mag, p_gate, p_phii, p_qoff,
                                      iscale, ln_g, ln_b, p_coff, p_ctxf);

    mma_gemm<3,1><<<gO1, blk, SMEM_BYTES>>>(p_ctxf, p_wf + OFF_O1, b_o1, 0, 0, p_hf, 2048, 1024);
    mma_gemm<4,0><<<gO2, blk, SMEM_BYTES>>>(p_hf,   p_wf + OFF_O2, b_o2, x, out, 0, 1024, 512);
}